// round 7
// baseline (speedup 1.0000x reference)
#include <cuda_runtime.h>
#include <cuda_bf16.h>
#include <math_constants.h>
#include <stdint.h>

// Problem constants
#define D      768
#define NA     4096
#define NC     50000
#define NCEN   10000
#define TK     16
#define TKP    32          // kept per split (slack for refine)

// splits
#define NSPLIT   16
#define CHUNK    (NC / NSPLIT)        // 3125
#define NSPLIT_C 8
#define CHUNK_C  (NCEN / NSPLIT_C)    // 1250

// MMA tiling
#define BM 128
#define BN 128
#define BK 32
#define NKC (D / BK)       // 24 k-chunks
#define SAPAD 40           // elems per smem row (80B stride, conflict-free frags)
#define STAGEB (BM * SAPAD * 2)   // 10240 bytes per operand stage

#define CAP 32             // per-pass append buffer (pass = 32 cols -> never overflows)

// ---- dynamic smem layout for k_topk (bytes) ----
#define OFF_AS   0
#define OFF_BS   (OFF_AS + 2 * STAGEB)          // 20480
#define OFF_TOPV (OFF_BS + 2 * STAGEB)          // 40960
#define OFF_TOPI (OFF_TOPV + BM * TKP * 4)      // 57344
#define OFF_BUFV (OFF_TOPI + BM * TKP * 4)      // 73728
#define OFF_BUFI (OFF_BUFV + BM * CAP * 4)      // 90112
#define OFF_TH   (OFF_BUFI + BM * CAP * 4)      // 106496
#define OFF_CNT  (OFF_TH + BM * 4)              // 107008
#define OFF_NF   (OFF_CNT + BM * 4)             // 107520
#define SMEM_TOPK (OFF_NF + BM * 4)             // 108032

// ---- dynamic smem layout for k_centers ----
#define OFF_REDV (OFF_BS + 2 * STAGEB)          // 40960
#define OFF_REDI (OFF_REDV + BM * 16 * 4)       // 49152
#define SMEM_CEN (OFF_REDI + BM * 16 * 4)       // 57344

// ---- scratch (static __device__ globals) ----
__device__ __align__(16) uint16_t g_Abf[NA * D];
__device__ __align__(16) uint16_t g_Candbf[(size_t)NC * D];
__device__ __align__(16) uint16_t g_Cenbf[NCEN * D];

__device__ float g_pv[NA * NSPLIT * TKP];
__device__ int   g_pi[NA * NSPLIT * TKP];
__device__ int   g_ridx[NA * TKP];
__device__ float g_cmv[NA * NSPLIT_C * 2];
__device__ int   g_cmi[NA * NSPLIT_C * 2];
__device__ float g_c2[NCEN];
__device__ int   g_fidx[NA * TK];

__device__ __forceinline__ bool precede(float v1, int i1, float v2, int i2) {
    return (v1 > v2) || (v1 == v2 && i1 < i2);
}
__device__ __forceinline__ bool preceded(double v1, int i1, double v2, int i2) {
    return (v1 > v2) || (v1 == v2 && i1 < i2);
}

__device__ __forceinline__ void mma16816(float* c, const uint32_t* a, const uint32_t* b) {
    asm volatile(
        "mma.sync.aligned.m16n8k16.row.col.f32.bf16.bf16.f32 "
        "{%0,%1,%2,%3}, {%4,%5,%6,%7}, {%8,%9}, {%0,%1,%2,%3};"
        : "+f"(c[0]), "+f"(c[1]), "+f"(c[2]), "+f"(c[3])
        : "r"(a[0]), "r"(a[1]), "r"(a[2]), "r"(a[3]), "r"(b[0]), "r"(b[1]));
}
__device__ __forceinline__ void cpz16(uint32_t dst, const void* src, bool ok) {
    asm volatile("cp.async.cg.shared.global [%0], [%1], 16, %2;"
                 :: "r"(dst), "l"(src), "r"(ok ? 16 : 0) : "memory");
}
#define CP_COMMIT()  asm volatile("cp.async.commit_group;" ::: "memory")
#define CP_WAIT(n)   asm volatile("cp.async.wait_group %0;" :: "n"(n) : "memory")

// ---------------------------------------------------------------------------
// float -> bf16 conversion (vectorized)
// ---------------------------------------------------------------------------
__global__ void k_cvt(const float4* __restrict__ s, uint2* __restrict__ d, int n4) {
    int i = blockIdx.x * blockDim.x + threadIdx.x;
    if (i >= n4) return;
    float4 v = s[i];
    __nv_bfloat162 p0 = __floats2bfloat162_rn(v.x, v.y);
    __nv_bfloat162 p1 = __floats2bfloat162_rn(v.z, v.w);
    uint2 o;
    o.x = *(uint32_t*)&p0;
    o.y = *(uint32_t*)&p1;
    d[i] = o;
}

// ---------------------------------------------------------------------------
// ||center||^2 precompute (fp32, pruning only)
// ---------------------------------------------------------------------------
__global__ void k_c2(const float* __restrict__ cen) {
    int w = (blockIdx.x * blockDim.x + threadIdx.x) >> 5;
    int lane = threadIdx.x & 31;
    if (w >= NCEN) return;
    const float* p = cen + (size_t)w * D;
    float s = 0.f;
    for (int k = lane; k < D; k += 32) { float x = p[k]; s += x * x; }
    #pragma unroll
    for (int o = 16; o; o >>= 1) s += __shfl_down_sync(0xffffffffu, s, o);
    if (lane == 0) g_c2[w] = s;
}

// ---------------------------------------------------------------------------
// chunk loader: A/B tiles [128 rows][32 bf16] into padded smem, stage st
// ---------------------------------------------------------------------------
__device__ __forceinline__ void load_chunk(char* sm, int st, int kt,
                                           int rowBase, int colBase, int colLimit,
                                           const uint16_t* __restrict__ Bsrc) {
    int tid = threadIdx.x;
    uint32_t sA = (uint32_t)__cvta_generic_to_shared(sm + OFF_AS + st * STAGEB);
    uint32_t sB = (uint32_t)__cvta_generic_to_shared(sm + OFF_BS + st * STAGEB);
    #pragma unroll
    for (int it = 0; it < 2; it++) {
        int u = tid + 256 * it;        // 0..511
        int r = u >> 2;                // row 0..127
        int q = u & 3;                 // 16B chunk within 64B row
        uint32_t off = (uint32_t)(r * SAPAD + q * 8) * 2;
        cpz16(sA + off, g_Abf + (size_t)(rowBase + r) * D + kt + q * 8, true);
        int gc = colBase + r;
        bool ok = gc < colLimit;
        cpz16(sB + off, Bsrc + (size_t)(ok ? gc : 0) * D + kt + q * 8, ok);
    }
    CP_COMMIT();
}

// ---------------------------------------------------------------------------
// MMA core for one chunk: warp tile 32x64, c[2][8][4]
// ---------------------------------------------------------------------------
__device__ __forceinline__ void mma_chunk(const uint16_t* __restrict__ Ab,
                                          const uint16_t* __restrict__ Bb,
                                          float c[2][8][4], int wm, int wn,
                                          int gid, int tig) {
    #pragma unroll
    for (int ks = 0; ks < 2; ks++) {
        int k0 = ks * 16;
        uint32_t af[2][4], fb[8][2];
        #pragma unroll
        for (int i = 0; i < 2; i++) {
            int r = wm * 32 + i * 16 + gid;
            af[i][0] = *(const uint32_t*)(Ab + r * SAPAD + k0 + 2 * tig);
            af[i][1] = *(const uint32_t*)(Ab + (r + 8) * SAPAD + k0 + 2 * tig);
            af[i][2] = *(const uint32_t*)(Ab + r * SAPAD + k0 + 8 + 2 * tig);
            af[i][3] = *(const uint32_t*)(Ab + (r + 8) * SAPAD + k0 + 8 + 2 * tig);
        }
        #pragma unroll
        for (int j = 0; j < 8; j++) {
            int n = wn * 64 + j * 8 + gid;
            fb[j][0] = *(const uint32_t*)(Bb + n * SAPAD + k0 + 2 * tig);
            fb[j][1] = *(const uint32_t*)(Bb + n * SAPAD + k0 + 8 + 2 * tig);
        }
        #pragma unroll
        for (int i = 0; i < 2; i++)
            #pragma unroll
            for (int j = 0; j < 8; j++)
                mma16816(c[i][j], af[i], fb[j]);
    }
}

// ---------------------------------------------------------------------------
// candidates GEMM + fused per-row top-32  grid (NA/128, NSPLIT), 256 thr
// ---------------------------------------------------------------------------
extern __shared__ __align__(16) char smraw[];

__global__ __launch_bounds__(256, 2)
void k_topk(void) {
    char* sm = smraw;
    float* topv   = (float*)(sm + OFF_TOPV);
    int*   topi   = (int*)(sm + OFF_TOPI);
    float* bufv   = (float*)(sm + OFF_BUFV);
    int*   bufi   = (int*)(sm + OFF_BUFI);
    float* thresh = (float*)(sm + OFF_TH);
    int*   cnt    = (int*)(sm + OFF_CNT);
    int*   nfill  = (int*)(sm + OFF_NF);

    int tid = threadIdx.x;
    int lane = tid & 31, wid = tid >> 5;
    int gid = lane >> 2, tig = lane & 3;
    int wm = wid & 3, wn = wid >> 2;

    int rowBase = blockIdx.x * BM;
    int split = blockIdx.y;
    int colStart = split * CHUNK;
    int colEnd = colStart + CHUNK;

    if (tid < BM) { thresh[tid] = -CUDART_INF_F; cnt[tid] = 0; nfill[tid] = 0; }
    __syncthreads();

    int nT = (CHUNK + BN - 1) / BN;
    for (int t = 0; t < nT; t++) {
        int colBase = colStart + t * BN;
        float c[2][8][4];
        #pragma unroll
        for (int i = 0; i < 2; i++)
            #pragma unroll
            for (int j = 0; j < 8; j++)
                #pragma unroll
                for (int f = 0; f < 4; f++) c[i][j][f] = 0.f;

        load_chunk(sm, 0, 0, rowBase, colBase, colEnd, g_Candbf);
        load_chunk(sm, 1, BK, rowBase, colBase, colEnd, g_Candbf);
        for (int kk = 0; kk < NKC; kk++) {
            int cur = kk & 1;
            if (kk + 1 < NKC) { CP_WAIT(1); } else { CP_WAIT(0); }
            __syncthreads();
            const uint16_t* Ab = (const uint16_t*)(sm + OFF_AS + cur * STAGEB);
            const uint16_t* Bb = (const uint16_t*)(sm + OFF_BS + cur * STAGEB);
            mma_chunk(Ab, Bb, c, wm, wn, gid, tig);
            __syncthreads();
            if (kk + 2 < NKC)
                load_chunk(sm, cur, (kk + 2) * BK, rowBase, colBase, colEnd, g_Candbf);
        }

        // ---- 4-pass epilogue: 32 columns per pass, compact after each ----
        #pragma unroll 1
        for (int pass = 0; pass < 4; pass++) {
            if (wn == (pass >> 1)) {
                int jb = (pass & 1) * 4;
                #pragma unroll
                for (int i = 0; i < 2; i++) {
                    #pragma unroll
                    for (int f = 0; f < 4; f++) {
                        int lr = wm * 32 + i * 16 + (f >> 1) * 8 + gid;
                        int grow = rowBase + lr;
                        float thv = thresh[lr];
                        #pragma unroll
                        for (int jj = 0; jj < 4; jj++) {
                            int j = jb + jj;
                            int gc = colBase + wn * 64 + j * 8 + 2 * tig + (f & 1);
                            float v = c[i][j][f];
                            if (gc < colEnd && gc != grow && v > thv) {
                                int slot = atomicAdd(&cnt[lr], 1);
                                if (slot < CAP) { bufv[lr * CAP + slot] = v; bufi[lr * CAP + slot] = gc; }
                            }
                        }
                    }
                }
            }
            __syncthreads();
            if (tid < BM) {
                int cc = cnt[tid];
                if (cc > 0) {
                    if (cc > CAP) cc = CAP;
                    int nf = nfill[tid];
                    float* tv = topv + tid * TKP;
                    int*   ti = topi + tid * TKP;
                    for (int s = 0; s < cc; s++) {
                        float v = bufv[tid * CAP + s];
                        int gi = bufi[tid * CAP + s];
                        if (nf == TKP && !precede(v, gi, tv[TKP - 1], ti[TKP - 1])) continue;
                        int p = (nf < TKP) ? nf : TKP - 1;
                        while (p > 0 && precede(v, gi, tv[p - 1], ti[p - 1])) {
                            tv[p] = tv[p - 1]; ti[p] = ti[p - 1]; p--;
                        }
                        tv[p] = v; ti[p] = gi;
                        if (nf < TKP) nf++;
                    }
                    nfill[tid] = nf;
                    cnt[tid] = 0;
                    if (nf == TKP) thresh[tid] = tv[TKP - 1];
                }
            }
            __syncthreads();
        }
    }
    if (tid < BM) {
        int row = rowBase + tid;
        int nf = nfill[tid];
        for (int k2 = 0; k2 < TKP; k2++) {
            g_pv[(row * NSPLIT + split) * TKP + k2] = (k2 < nf) ? topv[tid * TKP + k2] : -CUDART_INF_F;
            g_pi[(row * NSPLIT + split) * TKP + k2] = (k2 < nf) ? topi[tid * TKP + k2] : 0x7fffffff;
        }
    }
}

// ---------------------------------------------------------------------------
// centers GEMM + fused min-2 of (c2 - 2*dot)  grid (NA/128, NSPLIT_C)
// ---------------------------------------------------------------------------
__global__ __launch_bounds__(256, 2)
void k_centers(void) {
    char* sm = smraw;
    float* redv = (float*)(sm + OFF_REDV);
    int*   redi = (int*)(sm + OFF_REDI);

    int tid = threadIdx.x;
    int lane = tid & 31, wid = tid >> 5;
    int gid = lane >> 2, tig = lane & 3;
    int wm = wid & 3, wn = wid >> 2;

    int rowBase = blockIdx.x * BM;
    int split = blockIdx.y;
    int colStart = split * CHUNK_C;
    int colEnd = colStart + CHUNK_C;

    float bv0[4], bv1[4]; int bi0[4], bi1[4];
    #pragma unroll
    for (int i = 0; i < 4; i++) {
        bv0[i] = bv1[i] = CUDART_INF_F;
        bi0[i] = bi1[i] = 0x7fffffff;
    }

    int nT = (CHUNK_C + BN - 1) / BN;
    for (int t = 0; t < nT; t++) {
        int colBase = colStart + t * BN;
        float c[2][8][4];
        #pragma unroll
        for (int i = 0; i < 2; i++)
            #pragma unroll
            for (int j = 0; j < 8; j++)
                #pragma unroll
                for (int f = 0; f < 4; f++) c[i][j][f] = 0.f;

        load_chunk(sm, 0, 0, rowBase, colBase, colEnd, g_Cenbf);
        load_chunk(sm, 1, BK, rowBase, colBase, colEnd, g_Cenbf);
        for (int kk = 0; kk < NKC; kk++) {
            int cur = kk & 1;
            if (kk + 1 < NKC) { CP_WAIT(1); } else { CP_WAIT(0); }
            __syncthreads();
            const uint16_t* Ab = (const uint16_t*)(sm + OFF_AS + cur * STAGEB);
            const uint16_t* Bb = (const uint16_t*)(sm + OFF_BS + cur * STAGEB);
            mma_chunk(Ab, Bb, c, wm, wn, gid, tig);
            __syncthreads();
            if (kk + 2 < NKC)
                load_chunk(sm, cur, (kk + 2) * BK, rowBase, colBase, colEnd, g_Cenbf);
        }
        // min-2 update
        #pragma unroll
        for (int i = 0; i < 2; i++)
            #pragma unroll
            for (int f = 0; f < 4; f++) {
                int ri = i * 2 + (f >> 1);
                #pragma unroll
                for (int j = 0; j < 8; j++) {
                    int gc = colBase + wn * 64 + j * 8 + 2 * tig + (f & 1);
                    if (gc < colEnd) {
                        float v = g_c2[gc] - 2.0f * c[i][j][f];
                        if (v < bv0[ri] || (v == bv0[ri] && gc < bi0[ri])) {
                            bv1[ri] = bv0[ri]; bi1[ri] = bi0[ri];
                            bv0[ri] = v; bi0[ri] = gc;
                        } else if (v < bv1[ri] || (v == bv1[ri] && gc < bi1[ri])) {
                            bv1[ri] = v; bi1[ri] = gc;
                        }
                    }
                }
            }
    }

    // per-row reduction: 8 thread-columns (wn,tig) hold each row, 2 values each
    int sid = wn * 4 + tig;   // 0..7
    #pragma unroll
    for (int i = 0; i < 2; i++)
        #pragma unroll
        for (int hi = 0; hi < 2; hi++) {
            int ri = i * 2 + hi;
            int lr = wm * 32 + i * 16 + hi * 8 + gid;
            redv[lr * 16 + sid * 2 + 0] = bv0[ri];
            redi[lr * 16 + sid * 2 + 0] = bi0[ri];
            redv[lr * 16 + sid * 2 + 1] = bv1[ri];
            redi[lr * 16 + sid * 2 + 1] = bi1[ri];
        }
    __syncthreads();
    if (tid < BM) {
        float b0 = CUDART_INF_F, b1 = CUDART_INF_F;
        int i0 = 0x7fffffff, i1 = 0x7fffffff;
        for (int x = 0; x < 16; x++) {
            float v = redv[tid * 16 + x]; int ii = redi[tid * 16 + x];
            if (v < b0 || (v == b0 && ii < i0)) { b1 = b0; i1 = i0; b0 = v; i0 = ii; }
            else if (v < b1 || (v == b1 && ii < i1)) { b1 = v; i1 = ii; }
        }
        int row = rowBase + tid;
        g_cmv[(row * NSPLIT_C + split) * 2 + 0] = b0;
        g_cmi[(row * NSPLIT_C + split) * 2 + 0] = i0;
        g_cmv[(row * NSPLIT_C + split) * 2 + 1] = b1;
        g_cmi[(row * NSPLIT_C + split) * 2 + 1] = i1;
    }
}

// ---------------------------------------------------------------------------
// Merge topk partials: bitonic sort of 512 pairs/row, keep top-32
// ---------------------------------------------------------------------------
__global__ void k_mtopk() {
    __shared__ float sv[512];
    __shared__ int   si[512];
    int row = blockIdx.x;
    int tid = threadIdx.x;
    sv[tid] = g_pv[row * 512 + tid];
    si[tid] = g_pi[row * 512 + tid];
    __syncthreads();
    for (int k = 2; k <= 512; k <<= 1) {
        for (int j = k >> 1; j > 0; j >>= 1) {
            int ixj = tid ^ j;
            if (ixj > tid) {
                float v1 = sv[tid], v2 = sv[ixj];
                int i1 = si[tid], i2 = si[ixj];
                bool desc = ((tid & k) == 0);
                bool sw = desc ? precede(v2, i2, v1, i1) : precede(v1, i1, v2, i2);
                if (sw) { sv[tid] = v2; si[tid] = i2; sv[ixj] = v1; si[ixj] = i1; }
            }
            __syncthreads();
        }
    }
    if (tid < TKP) g_ridx[row * TKP + tid] = si[tid];
}

// ---------------------------------------------------------------------------
// compensated-fp32 dot product of one lane-strided slice
// (TwoProd via FMA + Neumaier running sum; near-exact ranking, no fp64 in loop)
// ---------------------------------------------------------------------------
__device__ __forceinline__ double comp_dot(const float* __restrict__ a,
                                           const float* __restrict__ b, int lane) {
    float s = 0.f, comp = 0.f;
    for (int k = lane; k < D; k += 32) {
        float x = a[k], y = b[k];
        float p = x * y;
        float e = fmaf(x, y, -p);          // exact product tail
        float t = s + p;
        comp += (fabsf(s) >= fabsf(p)) ? ((s - t) + p) : ((p - t) + s);
        s = t;
        comp += e;
    }
    return (double)s + (double)comp;
}

__device__ __forceinline__ double comp_dist2(const float* __restrict__ a,
                                             const float* __restrict__ b, int lane) {
    float s = 0.f, comp = 0.f;
    for (int k = lane; k < D; k += 32) {
        float d = a[k] - b[k];
        float p = d * d;
        float e = fmaf(d, d, -p);
        float t = s + p;
        comp += (fabsf(s) >= fabsf(p)) ? ((s - t) + p) : ((p - t) + s);
        s = t;
        comp += e;
    }
    return (double)s + (double)comp;
}

// ---------------------------------------------------------------------------
// refine top-32 sims -> exact top-16 (one block per anchor row)
// ---------------------------------------------------------------------------
__global__ __launch_bounds__(256)
void k_refine(const float* __restrict__ A, const float* __restrict__ Cand) {
    __shared__ double dv[TKP];
    __shared__ int    di[TKP];
    int row = blockIdx.x;
    int tid = threadIdx.x;
    int wid = tid >> 5, lane = tid & 31;
    const float* ar = A + (size_t)row * D;
    for (int c = wid; c < TKP; c += 8) {
        int idx = g_ridx[row * TKP + c];
        double s;
        if (idx >= 0 && idx < NC) {
            s = comp_dot(ar, Cand + (size_t)idx * D, lane);
        } else {
            s = (lane == 0) ? -CUDART_INF : 0.0;
        }
        #pragma unroll
        for (int o = 16; o; o >>= 1) s += __shfl_down_sync(0xffffffffu, s, o);
        if (lane == 0) { dv[c] = s; di[c] = idx; }
    }
    __syncthreads();
    if (tid == 0) {
        double tv[TK]; int ti[TK]; int nf = 0;
        for (int s = 0; s < TKP; s++) {
            double v = dv[s]; int gi = di[s];
            if (nf == TK && !preceded(v, gi, tv[TK - 1], ti[TK - 1])) continue;
            int p = (nf < TK) ? nf : TK - 1;
            while (p > 0 && preceded(v, gi, tv[p - 1], ti[p - 1])) {
                tv[p] = tv[p - 1]; ti[p] = ti[p - 1]; p--;
            }
            tv[p] = v; ti[p] = gi;
            if (nf < TK) nf++;
        }
        for (int k2 = 0; k2 < TK; k2++) g_fidx[row * TK + k2] = ti[k2];
    }
}

// ---------------------------------------------------------------------------
// refine 16 center candidates -> exact argmin + min_dist
// ---------------------------------------------------------------------------
__global__ __launch_bounds__(256)
void k_cenref(const float* __restrict__ A, const float* __restrict__ Cen,
              float* __restrict__ out) {
    __shared__ double dv[NSPLIT_C * 2];
    __shared__ int    di[NSPLIT_C * 2];
    int row = blockIdx.x;
    int tid = threadIdx.x;
    int wid = tid >> 5, lane = tid & 31;
    const float* ar = A + (size_t)row * D;
    for (int c = wid; c < NSPLIT_C * 2; c += 8) {
        int idx = g_cmi[row * NSPLIT_C * 2 + c];
        double s;
        if (idx >= 0 && idx < NCEN) {
            s = comp_dist2(ar, Cen + (size_t)idx * D, lane);
        } else {
            s = (lane == 0) ? CUDART_INF : 0.0;
        }
        #pragma unroll
        for (int o = 16; o; o >>= 1) s += __shfl_down_sync(0xffffffffu, s, o);
        if (lane == 0) { dv[c] = s; di[c] = idx; }
    }
    __syncthreads();
    if (tid == 0) {
        double best = CUDART_INF; int besti = 0x7fffffff;
        for (int s = 0; s < NSPLIT_C * 2; s++) {
            double v = dv[s]; int ii = di[s];
            if (v < best || (v == best && ii < besti)) { best = v; besti = ii; }
        }
        if (best < 0.0) best = 0.0;
        out[(size_t)NA * TK * D + row] = (float)besti;
        out[(size_t)NA * TK * D + NA + row] = (float)sqrt(best);
    }
}

// ---------------------------------------------------------------------------
// Gather: out[row][k][:] = candidates[idx][:]
// ---------------------------------------------------------------------------
__global__ void k_gather(const float* __restrict__ Cand, float* __restrict__ out) {
    int b = blockIdx.x;
    int t = threadIdx.x;
    int idx = g_fidx[b];
    const float4* c4 = (const float4*)(Cand + (size_t)idx * D);
    float4* o4 = (float4*)(out + (size_t)b * D);
    o4[t] = c4[t];
}

// ---------------------------------------------------------------------------
extern "C" void kernel_launch(void* const* d_in, const int* in_sizes, int n_in,
                              void* d_out, int out_size) {
    const float* A    = (const float*)d_in[0];   // anchors    [4096, 768]
    const float* Cand = (const float*)d_in[1];   // candidates [50000, 768]
    const float* Cen  = (const float*)d_in[2];   // centers    [10000, 768]
    float* out = (float*)d_out;

    cudaFuncSetAttribute(k_topk, cudaFuncAttributeMaxDynamicSharedMemorySize, SMEM_TOPK);
    cudaFuncSetAttribute(k_centers, cudaFuncAttributeMaxDynamicSharedMemorySize, SMEM_CEN);

    uint16_t *pAbf, *pCandbf, *pCenbf;
    cudaGetSymbolAddress((void**)&pAbf, g_Abf);
    cudaGetSymbolAddress((void**)&pCandbf, g_Candbf);
    cudaGetSymbolAddress((void**)&pCenbf, g_Cenbf);

    // 0) conversions to bf16
    k_cvt<<<(NA * D / 4 + 255) / 256, 256>>>((const float4*)A, (uint2*)pAbf, NA * D / 4);
    k_cvt<<<(NC * D / 4 + 255) / 256, 256>>>((const float4*)Cand, (uint2*)pCandbf, NC * D / 4);
    k_cvt<<<(NCEN * D / 4 + 255) / 256, 256>>>((const float4*)Cen, (uint2*)pCenbf, NCEN * D / 4);
    // 1) ||center||^2 (fp32)
    k_c2<<<(NCEN * 32 + 255) / 256, 256>>>(Cen);
    // 2) centers GEMM + min-2 pruning
    k_centers<<<dim3(NA / BM, NSPLIT_C), 256, SMEM_CEN>>>();
    // 3) candidates GEMM + top-32 pruning
    k_topk<<<dim3(NA / BM, NSPLIT), 256, SMEM_TOPK>>>();
    // 4) merge partials -> refine list
    k_mtopk<<<NA, 512>>>();
    // 5) exact top-16 (compensated fp32)
    k_refine<<<NA, 256>>>(A, Cand);
    // 6) exact argmin + min_dist
    k_cenref<<<NA, 256>>>(A, Cen, out);
    // 7) gather hard negatives
    k_gather<<<NA * TK, 192>>>(Cand, out);
}